// round 14
// baseline (speedup 1.0000x reference)
#include <cuda_runtime.h>
#include <math.h>

#define NROWS 16384
#define DIM   64
#define FULLMASK 0xffffffffu

#define A_BLOCKS 256     // bids [0, 256): compute t1 tiles (wave-1 resident)
#define B_BLOCKS 4096    // bids [256, 4352): 4 rows/block, 2 warps per row
#define CAP      128     // index-stack capacity per HALF-row (E[nnz]=16)
#define BATCH    4       // float4 per lane per scan iteration
#define NITER    16      // 2048 float4 per half-row / 32 lanes / BATCH
#define PF       4       // L2 prefetch distance (iterations)

// Scratch: t1[i][c] = (logmap0(x) @ W^T)[i][c+1], c = 0..62; column 63 = 0 pad.
__device__ float    g_t1[NROWS * DIM];
__device__ unsigned g_ready;   // zero-init at load; self-resets each launch
__device__ unsigned g_done;

struct SmemA { float xs[64][68]; float wt[64][68]; float ss[64]; };
struct SmemB { unsigned short stack[8][CAP]; float comb[8][64]; int ccnt[8]; };
union  SmemU { SmemA a; SmemB b; };

__global__ void __launch_bounds__(256, 4) lorentz_gnn_fused(
    const float* __restrict__ x, const float* __restrict__ W,
    const float* __restrict__ adj, float* __restrict__ out)
{
    __shared__ SmemU sm;
    const int tid  = threadIdx.x;
    const int warp = tid >> 5;
    const int lane = tid & 31;

    if (blockIdx.x < A_BLOCKS) {
        // ============ Phase A: t1 = s_i * (x[i,1:] @ W[1:,1:]^T) ============
        const int row0 = blockIdx.x * 64;

        #pragma unroll
        for (int p = 0; p < 16; p++) {
            int i = p * 4 + (tid >> 6);
            int j = tid & 63;
            sm.a.xs[j][i] = x[(size_t)(row0 + i) * DIM + j];
        }
        #pragma unroll
        for (int p = 0; p < 16; p++) {
            int j = p * 4 + (tid >> 6);
            int d = tid & 63;
            float w = W[j * DIM + d];
            if (j >= 1) sm.a.wt[d][j - 1] = (d == 0) ? 0.f : w;
        }
        if (tid < 64) sm.a.wt[tid][63] = 0.f;   // pad output col 63 -> 0
        __syncthreads();

        if (tid < 64) {
            float nn = 0.f;
            #pragma unroll
            for (int d = 1; d < 64; d++) { float v = sm.a.xs[d][tid]; nn += v * v; }
            float yn    = fmaxf(sqrtf(nn), 1e-15f);
            float theta = fmaxf(sm.a.xs[0][tid], 1.0f + 1e-7f);
            sm.a.ss[tid] = acoshf(theta) / yn;
        }
        __syncthreads();

        const int tx = tid & 15, ty = tid >> 4;
        float acc[4][4] = {};
        #pragma unroll
        for (int d = 0; d < 64; d++) {
            float4 xv = *(const float4*)&sm.a.xs[d][ty * 4];
            float4 wv = *(const float4*)&sm.a.wt[d][tx * 4];
            acc[0][0] += xv.x * wv.x; acc[0][1] += xv.x * wv.y;
            acc[0][2] += xv.x * wv.z; acc[0][3] += xv.x * wv.w;
            acc[1][0] += xv.y * wv.x; acc[1][1] += xv.y * wv.y;
            acc[1][2] += xv.y * wv.z; acc[1][3] += xv.y * wv.w;
            acc[2][0] += xv.z * wv.x; acc[2][1] += xv.z * wv.y;
            acc[2][2] += xv.z * wv.z; acc[2][3] += xv.z * wv.w;
            acc[3][0] += xv.w * wv.x; acc[3][1] += xv.w * wv.y;
            acc[3][2] += xv.w * wv.z; acc[3][3] += xv.w * wv.w;
        }
        #pragma unroll
        for (int rr = 0; rr < 4; rr++) {
            int   r = ty * 4 + rr;
            float s = sm.a.ss[r];
            float4 o = make_float4(acc[rr][0] * s, acc[rr][1] * s,
                                   acc[rr][2] * s, acc[rr][3] * s);
            *(float4*)&g_t1[(size_t)(row0 + r) * DIM + tx * 4] = o;
        }

        __threadfence();
        __syncthreads();
        if (tid == 0) atomicAdd(&g_ready, 1u);
        return;
    }

    // ====== Phase B: 2 warps per row (half each), scan -> gather -> combine =
    const int wr   = warp >> 1;          // row-in-block 0..3
    const int half = warp & 1;           // which half of the row
    const int row  = (blockIdx.x - A_BLOCKS) * 4 + wr;
    unsigned short* stk = sm.b.stack[warp];

    // Half-row base: row*4096 float4 + half*2048 float4.
    const float4* __restrict__ a4 =
        reinterpret_cast<const float4*>(adj) + (size_t)row * (NROWS / 4)
        + (size_t)half * (NROWS / 8);
    const int cbase = half * (NITER * BATCH);   // global chunk offset

    // Warm the L2 prefetch pipe.
    #pragma unroll
    for (int p = 1; p <= PF; p++)
        #pragma unroll
        for (int u = 0; u < BATCH; u++)
            asm volatile("prefetch.global.L2 [%0];"
                         :: "l"(&a4[(p * BATCH + u) * 32 + lane]));

    float4 cur[BATCH], nxt[BATCH];
    #pragma unroll
    for (int u = 0; u < BATCH; u++)
        cur[u] = __ldcs(&a4[u * 32 + lane]);

    int cnt = 0;                         // uniform across the warp
    const unsigned below = (1u << lane) - 1u;

    #pragma unroll 1
    for (int it = 0; it < NITER; it++) {
        if (it + PF + 1 < NITER)
            #pragma unroll
            for (int u = 0; u < BATCH; u++)
                asm volatile("prefetch.global.L2 [%0];"
                             :: "l"(&a4[((it + PF + 1) * BATCH + u) * 32 + lane]));
        if (it < NITER - 1)
            #pragma unroll
            for (int u = 0; u < BATCH; u++)
                nxt[u] = __ldcs(&a4[((it + 1) * BATCH + u) * 32 + lane]);

        #pragma unroll
        for (int u = 0; u < BATCH; u++) {
            float4 v = cur[u];
            // entries >= 0: sum > 0 <=> any nonzero (no cancellation)
            float s = (v.x + v.y) + (v.z + v.w);
            unsigned any = __ballot_sync(FULLMASK, s > 0.f);
            if (any) {
                unsigned mx = __ballot_sync(FULLMASK, v.x != 0.f);
                unsigned my = __ballot_sync(FULLMASK, v.y != 0.f);
                unsigned mz = __ballot_sync(FULLMASK, v.z != 0.f);
                unsigned mw = __ballot_sync(FULLMASK, v.w != 0.f);
                int j0 = (((cbase + it * BATCH + u) * 32) + lane) * 4;
                int p  = cnt;
                if (v.x != 0.f) { int q = p + __popc(mx & below);
                                  if (q < CAP) stk[q] = (unsigned short)(j0 + 0); }
                p += __popc(mx);
                if (v.y != 0.f) { int q = p + __popc(my & below);
                                  if (q < CAP) stk[q] = (unsigned short)(j0 + 1); }
                p += __popc(my);
                if (v.z != 0.f) { int q = p + __popc(mz & below);
                                  if (q < CAP) stk[q] = (unsigned short)(j0 + 2); }
                p += __popc(mz);
                if (v.w != 0.f) { int q = p + __popc(mw & below);
                                  if (q < CAP) stk[q] = (unsigned short)(j0 + 3); }
                cnt = p + __popc(mw);
            }
        }
        #pragma unroll
        for (int u = 0; u < BATCH; u++) cur[u] = nxt[u];
    }

    // Acquire: wait until all A blocks have published t1 (long done by now).
    if (lane == 0)
        while (atomicAdd(&g_ready, 0u) < (unsigned)A_BLOCKS) __nanosleep(64);
    __syncwarp();
    __threadfence();

    // Gather partial (unscaled) sums for this half-row.
    int n = min(cnt, CAP);
    float a0 = 0.f, a1 = 0.f, b0 = 0.f, b1 = 0.f;
    float c0 = 0.f, c1 = 0.f, d0 = 0.f, d1 = 0.f;
    int k = 0;
    for (; k + 4 <= n; k += 4) {
        const float* p0 = g_t1 + (size_t)stk[k + 0] * DIM;
        const float* p1 = g_t1 + (size_t)stk[k + 1] * DIM;
        const float* p2 = g_t1 + (size_t)stk[k + 2] * DIM;
        const float* p3 = g_t1 + (size_t)stk[k + 3] * DIM;
        a0 += __ldcg(p0 + lane); a1 += __ldcg(p0 + lane + 32);
        b0 += __ldcg(p1 + lane); b1 += __ldcg(p1 + lane + 32);
        c0 += __ldcg(p2 + lane); c1 += __ldcg(p2 + lane + 32);
        d0 += __ldcg(p3 + lane); d1 += __ldcg(p3 + lane + 32);
    }
    for (; k < n; k++) {
        const float* p0 = g_t1 + (size_t)stk[k] * DIM;
        a0 += __ldcg(p0 + lane); a1 += __ldcg(p0 + lane + 32);
    }
    float s0 = (a0 + b0) + (c0 + d0);
    float s1 = (a1 + b1) + (c1 + d1);

    // Combine the two half-row partials via smem.
    sm.b.comb[warp][lane]      = s0;
    sm.b.comb[warp][lane + 32] = s1;
    if (lane == 0) sm.b.ccnt[warp] = n;
    __syncthreads();

    if (half == 0) {
        float t0 = s0 + sm.b.comb[warp + 1][lane];
        float t1v = s1 + sm.b.comb[warp + 1][lane + 32];
        int  nt  = n + sm.b.ccnt[warp + 1];
        float inv  = (nt > 0) ? (1.0f / (float)nt) : 0.f;
        float acc0 = t0 * inv;
        float acc1 = t1v * inv;

        // Epilogue: r = relu(m); out = [sqrt(1+sinh^2(rn)), sinh(rn)*r/rn]
        float r0 = fmaxf(acc0, 0.f);
        float r1 = fmaxf(acc1, 0.f);
        float nn = r0 * r0 + r1 * r1;
        #pragma unroll
        for (int o = 16; o; o >>= 1)
            nn += __shfl_xor_sync(FULLMASK, nn, o);

        float rn    = sqrtf(nn);
        float xn    = fmaxf(rn, 1e-15f);
        float sh    = sinhf(xn);
        float scale = sh / xn;
        float first = sqrtf(fmaxf(1.0f + sh * sh, 1e-15f));

        float* o = out + (size_t)row * DIM;
        if (lane == 0) o[0] = first;
        o[1 + lane] = scale * r0;
        if (lane < 31) o[33 + lane] = scale * r1;
    }

    // Self-reset for the next graph replay: last B block clears both flags.
    __syncthreads();
    if (tid == 0) {
        unsigned old = atomicAdd(&g_done, 1u);
        if (old == (unsigned)(B_BLOCKS - 1)) {
            atomicExch(&g_ready, 0u);
            atomicExch(&g_done, 0u);
        }
    }
}

// ---------------------------------------------------------------------------
extern "C" void kernel_launch(void* const* d_in, const int* in_sizes, int n_in,
                              void* d_out, int out_size)
{
    const float *x = nullptr, *adj = nullptr, *W = nullptr;
    for (int k = 0; k < n_in; k++) {
        long long n = in_sizes[k];
        if (n == (long long)NROWS * NROWS)      adj = (const float*)d_in[k];
        else if (n == (long long)DIM * DIM)     W   = (const float*)d_in[k];
        else if (n == (long long)NROWS * DIM)   x   = (const float*)d_in[k];
    }
    float* out = (float*)d_out;

    lorentz_gnn_fused<<<A_BLOCKS + B_BLOCKS, 256>>>(x, W, adj, out);
}

// round 15
// speedup vs baseline: 1.0794x; 1.0794x over previous
#include <cuda_runtime.h>
#include <math.h>

#define NROWS 16384
#define DIM   64
#define FULLMASK 0xffffffffu

#define A_BLOCKS 256     // bids [0, 256): compute t1 tiles (wave-1 resident)
#define B_BLOCKS 2048    // bids [256, 2304): one warp per output row
#define CAP      192     // index-stack capacity per row (E[nnz]=32, sigma~5.7)
#define BATCH    4       // float4 per lane per scan iteration
#define PF       4       // L2 prefetch distance (iterations)

// Scratch: t1[i][c] = (logmap0(x) @ W^T)[i][c+1], c = 0..62; column 63 = 0 pad.
__device__ float    g_t1[NROWS * DIM];
__device__ unsigned g_ready;   // zero-init at load; self-resets each launch
__device__ unsigned g_done;

struct SmemA { float xs[64][68]; float wt[64][68]; float ss[64]; };
struct SmemB { unsigned short stack[8][CAP]; };
union  SmemU { SmemA a; SmemB b; };

__global__ void __launch_bounds__(256, 4) lorentz_gnn_fused(
    const float* __restrict__ x, const float* __restrict__ W,
    const float* __restrict__ adj, float* __restrict__ out)
{
    __shared__ SmemU sm;
    const int tid  = threadIdx.x;
    const int warp = tid >> 5;
    const int lane = tid & 31;

    if (blockIdx.x < A_BLOCKS) {
        // ============ Phase A: t1 = s_i * (x[i,1:] @ W[1:,1:]^T) ============
        const int row0 = blockIdx.x * 64;

        #pragma unroll
        for (int p = 0; p < 16; p++) {
            int i = p * 4 + (tid >> 6);
            int j = tid & 63;
            sm.a.xs[j][i] = x[(size_t)(row0 + i) * DIM + j];
        }
        #pragma unroll
        for (int p = 0; p < 16; p++) {
            int j = p * 4 + (tid >> 6);
            int d = tid & 63;
            float w = W[j * DIM + d];
            if (j >= 1) sm.a.wt[d][j - 1] = (d == 0) ? 0.f : w;
        }
        if (tid < 64) sm.a.wt[tid][63] = 0.f;   // pad output col 63 -> 0
        __syncthreads();

        if (tid < 64) {
            float nn = 0.f;
            #pragma unroll
            for (int d = 1; d < 64; d++) { float v = sm.a.xs[d][tid]; nn += v * v; }
            float yn    = fmaxf(sqrtf(nn), 1e-15f);
            float theta = fmaxf(sm.a.xs[0][tid], 1.0f + 1e-7f);
            sm.a.ss[tid] = acoshf(theta) / yn;
        }
        __syncthreads();

        const int tx = tid & 15, ty = tid >> 4;
        float acc[4][4] = {};
        #pragma unroll
        for (int d = 0; d < 64; d++) {
            float4 xv = *(const float4*)&sm.a.xs[d][ty * 4];
            float4 wv = *(const float4*)&sm.a.wt[d][tx * 4];
            acc[0][0] += xv.x * wv.x; acc[0][1] += xv.x * wv.y;
            acc[0][2] += xv.x * wv.z; acc[0][3] += xv.x * wv.w;
            acc[1][0] += xv.y * wv.x; acc[1][1] += xv.y * wv.y;
            acc[1][2] += xv.y * wv.z; acc[1][3] += xv.y * wv.w;
            acc[2][0] += xv.z * wv.x; acc[2][1] += xv.z * wv.y;
            acc[2][2] += xv.z * wv.z; acc[2][3] += xv.z * wv.w;
            acc[3][0] += xv.w * wv.x; acc[3][1] += xv.w * wv.y;
            acc[3][2] += xv.w * wv.z; acc[3][3] += xv.w * wv.w;
        }
        #pragma unroll
        for (int rr = 0; rr < 4; rr++) {
            int   r = ty * 4 + rr;
            float s = sm.a.ss[r];
            float4 o = make_float4(acc[rr][0] * s, acc[rr][1] * s,
                                   acc[rr][2] * s, acc[rr][3] * s);
            *(float4*)&g_t1[(size_t)(row0 + r) * DIM + tx * 4] = o;
        }

        // Release: every thread fences its own t1 stores, then one arrival.
        __threadfence();
        __syncthreads();
        if (tid == 0) atomicAdd(&g_ready, 1u);
        return;
    }

    // ================= Phase B: scan adj row, then gather ==================
    const int row = (blockIdx.x - A_BLOCKS) * 8 + warp;
    unsigned short* stk = sm.b.stack[warp];

    const float4* __restrict__ a4 =
        reinterpret_cast<const float4*>(adj) + (size_t)row * (NROWS / 4);

    // Warm the L2 prefetch pipe.
    #pragma unroll
    for (int p = 1; p <= PF; p++)
        #pragma unroll
        for (int u = 0; u < BATCH; u++)
            asm volatile("prefetch.global.L2 [%0];"
                         :: "l"(&a4[(p * BATCH + u) * 32 + lane]));

    float4 cur[BATCH], nxt[BATCH];
    #pragma unroll
    for (int u = 0; u < BATCH; u++)
        cur[u] = __ldcs(&a4[u * 32 + lane]);

    int cnt = 0;                         // uniform across the warp
    const unsigned below = (1u << lane) - 1u;

    #pragma unroll 1
    for (int it = 0; it < 32; it++) {
        if (it + PF + 1 < 32)
            #pragma unroll
            for (int u = 0; u < BATCH; u++)
                asm volatile("prefetch.global.L2 [%0];"
                             :: "l"(&a4[((it + PF + 1) * BATCH + u) * 32 + lane]));
        if (it < 31)
            #pragma unroll
            for (int u = 0; u < BATCH; u++)
                nxt[u] = __ldcs(&a4[((it + 1) * BATCH + u) * 32 + lane]);

        #pragma unroll
        for (int u = 0; u < BATCH; u++) {
            float4 v = cur[u];
            // entries >= 0: sum > 0 <=> any nonzero (no cancellation)
            float s = (v.x + v.y) + (v.z + v.w);
            unsigned any = __ballot_sync(FULLMASK, s > 0.f);
            if (any) {
                unsigned mx = __ballot_sync(FULLMASK, v.x != 0.f);
                unsigned my = __ballot_sync(FULLMASK, v.y != 0.f);
                unsigned mz = __ballot_sync(FULLMASK, v.z != 0.f);
                unsigned mw = __ballot_sync(FULLMASK, v.w != 0.f);
                int j0 = ((it * BATCH + u) * 32 + lane) * 4;
                int p  = cnt;
                if (v.x != 0.f) { int q = p + __popc(mx & below);
                                  if (q < CAP) stk[q] = (unsigned short)(j0 + 0); }
                p += __popc(mx);
                if (v.y != 0.f) { int q = p + __popc(my & below);
                                  if (q < CAP) stk[q] = (unsigned short)(j0 + 1); }
                p += __popc(my);
                if (v.z != 0.f) { int q = p + __popc(mz & below);
                                  if (q < CAP) stk[q] = (unsigned short)(j0 + 2); }
                p += __popc(mz);
                if (v.w != 0.f) { int q = p + __popc(mw & below);
                                  if (q < CAP) stk[q] = (unsigned short)(j0 + 3); }
                cnt = p + __popc(mw);
            }
        }
        #pragma unroll
        for (int u = 0; u < BATCH; u++) cur[u] = nxt[u];
    }

    // Acquire: wait until all A blocks have published t1 (long done by now).
    if (lane == 0)
        while (atomicAdd(&g_ready, 0u) < (unsigned)A_BLOCKS) __nanosleep(64);
    __syncwarp();
    __threadfence();

    // Gather: m = (sum of t1 rows) / deg. 4 independent accumulator pairs.
    int n = min(cnt, CAP);
    float a0 = 0.f, a1 = 0.f, b0 = 0.f, b1 = 0.f;
    float c0 = 0.f, c1 = 0.f, d0 = 0.f, d1 = 0.f;
    int k = 0;
    for (; k + 4 <= n; k += 4) {
        const float* p0 = g_t1 + (size_t)stk[k + 0] * DIM;
        const float* p1 = g_t1 + (size_t)stk[k + 1] * DIM;
        const float* p2 = g_t1 + (size_t)stk[k + 2] * DIM;
        const float* p3 = g_t1 + (size_t)stk[k + 3] * DIM;
        a0 += __ldcg(p0 + lane); a1 += __ldcg(p0 + lane + 32);
        b0 += __ldcg(p1 + lane); b1 += __ldcg(p1 + lane + 32);
        c0 += __ldcg(p2 + lane); c1 += __ldcg(p2 + lane + 32);
        d0 += __ldcg(p3 + lane); d1 += __ldcg(p3 + lane + 32);
    }
    for (; k < n; k++) {
        const float* p0 = g_t1 + (size_t)stk[k] * DIM;
        a0 += __ldcg(p0 + lane); a1 += __ldcg(p0 + lane + 32);
    }
    float inv  = (n > 0) ? (1.0f / (float)n) : 0.f;
    float acc0 = ((a0 + b0) + (c0 + d0)) * inv;
    float acc1 = ((a1 + b1) + (c1 + d1)) * inv;

    // Epilogue: r = relu(m); out = [sqrt(1+sinh^2(rn)), sinh(rn)*r/rn]
    float r0 = fmaxf(acc0, 0.f);
    float r1 = fmaxf(acc1, 0.f);
    float nn = r0 * r0 + r1 * r1;
    #pragma unroll
    for (int o = 16; o; o >>= 1)
        nn += __shfl_xor_sync(FULLMASK, nn, o);

    float rn    = sqrtf(nn);
    float xn    = fmaxf(rn, 1e-15f);
    float sh    = sinhf(xn);
    float scale = sh / xn;
    float first = sqrtf(fmaxf(1.0f + sh * sh, 1e-15f));

    float* o = out + (size_t)row * DIM;
    if (lane == 0) o[0] = first;
    o[1 + lane] = scale * r0;
    if (lane < 31) o[33 + lane] = scale * r1;

    // Self-reset for the next graph replay: last B block clears both flags.
    __syncthreads();
    if (tid == 0) {
        unsigned old = atomicAdd(&g_done, 1u);
        if (old == (unsigned)(B_BLOCKS - 1)) {
            atomicExch(&g_ready, 0u);
            atomicExch(&g_done, 0u);
        }
    }
}

// ---------------------------------------------------------------------------
extern "C" void kernel_launch(void* const* d_in, const int* in_sizes, int n_in,
                              void* d_out, int out_size)
{
    const float *x = nullptr, *adj = nullptr, *W = nullptr;
    for (int k = 0; k < n_in; k++) {
        long long n = in_sizes[k];
        if (n == (long long)NROWS * NROWS)      adj = (const float*)d_in[k];
        else if (n == (long long)DIM * DIM)     W   = (const float*)d_in[k];
        else if (n == (long long)NROWS * DIM)   x   = (const float*)d_in[k];
    }
    float* out = (float*)d_out;

    lorentz_gnn_fused<<<A_BLOCKS + B_BLOCKS, 256>>>(x, W, adj, out);
}